// round 11
// baseline (speedup 1.0000x reference)
#include <cuda_runtime.h>
#include <cuda_fp16.h>
#include <math.h>
#include <stdint.h>

constexpr int kB  = 8;
constexpr int kNQ = 4096;
constexpr int kNS = 4096;
constexpr int kC  = 2048;
constexpr int kD  = 512;
constexpr int kMQ = kB * kNQ;   // 32768
constexpr int kMK = kB * kNS;   // 32768

// Scratch (__device__ globals; allocation-free rule)
__device__ __half g_ah[(size_t)kMQ * kC];        // q hi -> later qp hi
__device__ __half g_bh[(size_t)kMK * kC];        // k hi -> later kp hi
__device__ __half g_eh[(size_t)kC * kC];         // E = W - I, fp16
__device__ __half g_vt[(size_t)kB * kD * kNS];   // v transposed [b, d, s] fp16
__device__ __half g_ph[(size_t)kMQ * kNS];       // NORMALIZED attn weights fp16
__device__ float  g_qp[(size_t)kMQ * kC];
__device__ float  g_kp[(size_t)kMK * kC];
__device__ float  g_part[(size_t)kMQ * 32];      // per-(row, col-block) partial sums
__device__ float  g_rowsum[kMQ];

// ---------------- helpers ----------------
__device__ __forceinline__ uint32_t smem_u32(const void* p) {
    uint32_t a;
    asm("{ .reg .u64 t; cvta.to.shared.u64 t, %1; cvt.u32.u64 %0, t; }" : "=r"(a) : "l"(p));
    return a;
}
__device__ __forceinline__ void ldm4(uint32_t r[4], uint32_t addr) {
    asm volatile("ldmatrix.sync.aligned.m8n8.x4.shared.b16 {%0,%1,%2,%3}, [%4];"
                 : "=r"(r[0]), "=r"(r[1]), "=r"(r[2]), "=r"(r[3]) : "r"(addr));
}
__device__ __forceinline__ void mma16816(float c[4], const uint32_t a[4],
                                         uint32_t b0, uint32_t b1) {
    asm volatile(
        "mma.sync.aligned.m16n8k16.row.col.f32.f16.f16.f32 "
        "{%0,%1,%2,%3}, {%4,%5,%6,%7}, {%8,%9}, {%0,%1,%2,%3};"
        : "+f"(c[0]), "+f"(c[1]), "+f"(c[2]), "+f"(c[3])
        : "r"(a[0]), "r"(a[1]), "r"(a[2]), "r"(a[3]), "r"(b0), "r"(b1));
}

// Fast exp on the FMA/ALU pipes. Masked entries (t ~ -1000) -> exactly 0.0f.
__device__ __forceinline__ float fexp(float t) {
    const float u = fmaxf(t * 1.44269504f, -140.0f);
    const float fl = floorf(u);
    const float f = u - fl;
    float p = 1.5405930e-4f;
    p = fmaf(p, f, 1.3333558e-3f);
    p = fmaf(p, f, 9.6181291e-3f);
    p = fmaf(p, f, 5.5504109e-2f);
    p = fmaf(p, f, 2.4022651e-1f);
    p = fmaf(p, f, 6.9314718e-1f);
    p = fmaf(p, f, 1.0f);
    const int i = (int)fl;
    const float s = __int_as_float(max(i + 127, 0) << 23);
    return p * s;
}

// Tile geometry: block 128x128, BK=64 fp16, rows padded to 144 B (conflict-free)
// 4 warps (128 threads) as 2(m) x 2(n): warp tile 64x64 -> 1.5x less LDSM traffic
constexpr int BK = 64;
constexpr uint32_t ROWB = 144;
constexpr uint32_t TS   = 128 * ROWB;          // 18432 B per tile
constexpr unsigned SMEM_GM = 6 * TS;           // 110592: 3 stages x (A + B)

// Load a 128 x 64 (fp16) K-major tile into padded SMEM via cp.async (16B chunks)
// 128 threads: 8 iterations over 1024 chunks.
__device__ __forceinline__ void load_tile(uint32_t dst, const __half* src, int ldk) {
    const int tid = threadIdx.x;
    #pragma unroll
    for (int i = 0; i < 8; ++i) {
        const int idx = tid + i * 128;
        const int row = idx >> 3;
        const int seg = idx & 7;
        asm volatile("cp.async.cg.shared.global [%0], [%1], 16;"
                     :: "r"(dst + row * ROWB + seg * 16),
                        "l"(src + (size_t)row * ldk + seg * 8) : "memory");
    }
}

// ---------------------------------------------------------------------------
// HMMA mainloop: acc[4][8][4] accumulates C[128][128] = A * B^T.
// 4 warps as 2(m) x 2(n); warp tile 64x64. 3-stage cp.async pipeline.
// ---------------------------------------------------------------------------
__device__ __forceinline__ void hmma_mainloop(
    const __half* A, const __half* B, int lda, int ldb, int K,
    char* smem, float acc[4][8][4])
{
    const int tid  = threadIdx.x;
    const int wid  = tid >> 5;
    const int lane = tid & 31;
    const int wm   = wid >> 1;      // 0..1 -> m offset wm*64
    const int wn   = wid & 1;       // 0..1 -> n offset wn*64
    constexpr uint32_t STAGE = 2 * TS;
    const uint32_t sb = smem_u32(smem);
    const int NK = K / BK;

    load_tile(sb, A, lda);
    load_tile(sb + TS, B, ldb);
    asm volatile("cp.async.commit_group;");
    load_tile(sb + STAGE, A + BK, lda);
    load_tile(sb + STAGE + TS, B + BK, ldb);
    asm volatile("cp.async.commit_group;");

    const uint32_t lane_off = (uint32_t)((lane & 15) * ROWB + ((lane >> 4) * 8) * 2);

    for (int kc = 0; kc < NK; ++kc) {
        if (kc + 1 < NK) asm volatile("cp.async.wait_group 1;");
        else             asm volatile("cp.async.wait_group 0;");
        __syncthreads();

        if (kc + 2 < NK) {
            const uint32_t s = sb + ((kc + 2) % 3) * STAGE;
            const size_t k0 = (size_t)(kc + 2) * BK;
            load_tile(s, A + k0, lda);
            load_tile(s + TS, B + k0, ldb);
            asm volatile("cp.async.commit_group;");
        }

        const uint32_t base  = sb + (kc % 3) * STAGE;
        const uint32_t abase = base + wm * 64 * ROWB + lane_off;
        const uint32_t bbase = base + TS + wn * 64 * ROWB + lane_off;

        #pragma unroll
        for (int ks = 0; ks < 4; ++ks) {
            const uint32_t kb = ks * 32;
            uint32_t ah[4][4], bh[4][4];
            #pragma unroll
            for (int mt = 0; mt < 4; ++mt)
                ldm4(ah[mt], abase + mt * 16 * ROWB + kb);
            #pragma unroll
            for (int np = 0; np < 4; ++np)
                ldm4(bh[np], bbase + np * 16 * ROWB + kb);
            #pragma unroll
            for (int mt = 0; mt < 4; ++mt)
                #pragma unroll
                for (int np = 0; np < 4; ++np)
                    #pragma unroll
                    for (int h = 0; h < 2; ++h)
                        mma16816(acc[mt][np * 2 + h], ah[mt], bh[np][h], bh[np][h + 2]);
        }
    }
    __syncthreads();   // protect smem before epilogue reuse
}

// ---------------- GEMM kernels ----------------
// Projection: Y[m,n] = x[m,n] + sum_c xh[m,c]*E[n,c] + bias[n]   (E = W - I)
__global__ __launch_bounds__(128, 2)
void gemm_proj_k(const __half* __restrict__ Xh, const __half* __restrict__ Eh,
                 const float* __restrict__ x32, const float* __restrict__ bias,
                 float* __restrict__ Y) {
    extern __shared__ char smem[];
    const int m0 = blockIdx.y * 128, n0 = blockIdx.x * 128;
    float acc[4][8][4] = {};
    hmma_mainloop(Xh + (size_t)m0 * kC, Eh + (size_t)n0 * kC, kC, kC, kC, smem, acc);
    const int wid = threadIdx.x >> 5, lane = threadIdx.x & 31;
    const int wm = wid >> 1, wn = wid & 1;
    #pragma unroll
    for (int mt = 0; mt < 4; ++mt)
        #pragma unroll
        for (int nt = 0; nt < 8; ++nt) {
            const int r0 = m0 + wm * 64 + mt * 16 + (lane >> 2);
            const int c  = n0 + wn * 64 + nt * 8 + (lane & 3) * 2;
            const float* a = acc[mt][nt];
            const float2 x0 = *(const float2*)(x32 + (size_t)r0 * kC + c);
            const float2 x1 = *(const float2*)(x32 + (size_t)(r0 + 8) * kC + c);
            *(float2*)(Y + (size_t)r0 * kC + c) =
                make_float2(a[0] + x0.x + bias[c], a[1] + x0.y + bias[c + 1]);
            *(float2*)(Y + (size_t)(r0 + 8) * kC + c) =
                make_float2(a[2] + x1.x + bias[c], a[3] + x1.y + bias[c + 1]);
        }
}

// QK^T + exp epilogue + deterministic per-block partial row sums
__global__ __launch_bounds__(128, 2)
void gemm_attn_k(const __half* __restrict__ qh, const __half* __restrict__ kh,
                 const float* __restrict__ mask, const float* __restrict__ scale_ptr,
                 float* __restrict__ P32, float* __restrict__ part) {
    extern __shared__ char smem[];
    const int b = blockIdx.z;
    const int m0 = blockIdx.y * 128, n0 = blockIdx.x * 128;
    const size_t aoff = ((size_t)b * kNQ + m0) * kC;
    const size_t boff = ((size_t)b * kNS + n0) * kC;
    float acc[4][8][4] = {};
    hmma_mainloop(qh + aoff, kh + boff, kC, kC, kC, smem, acc);
    const int wid = threadIdx.x >> 5, lane = threadIdx.x & 31;
    const int wm = wid >> 1, wn = wid & 1;
    const float sc = scale_ptr[0];
    float srow[4][2] = {};
    #pragma unroll
    for (int mt = 0; mt < 4; ++mt)
        #pragma unroll
        for (int nt = 0; nt < 8; ++nt) {
            const int r0 = m0 + wm * 64 + mt * 16 + (lane >> 2);
            const int c  = n0 + wn * 64 + nt * 8 + (lane & 3) * 2;
            const float* a = acc[mt][nt];
            const float mk0 = mask[(size_t)b * kNS + c];
            const float mk1 = mask[(size_t)b * kNS + c + 1];
            const float e0 = fexp(sc * a[0] - sc - 1000.0f * mk0);
            const float e1 = fexp(sc * a[1] - sc - 1000.0f * mk1);
            const float e2 = fexp(sc * a[2] - sc - 1000.0f * mk0);
            const float e3 = fexp(sc * a[3] - sc - 1000.0f * mk1);
            const size_t rb0 = ((size_t)b * kNQ + r0) * kNS + c;
            const size_t rb1 = rb0 + (size_t)8 * kNS;
            *(float2*)(P32 + rb0) = make_float2(e0, e1);
            *(float2*)(P32 + rb1) = make_float2(e2, e3);
            srow[mt][0] += e0 + e1;
            srow[mt][1] += e2 + e3;
        }
    // deterministic block-level row sums: quad shuffle -> smem -> combine halves
    float* psum = (float*)smem;   // [128][2]
    #pragma unroll
    for (int mt = 0; mt < 4; ++mt)
        #pragma unroll
        for (int h = 0; h < 2; ++h) {
            float s = srow[mt][h];
            s += __shfl_down_sync(0xffffffffu, s, 1);
            s += __shfl_down_sync(0xffffffffu, s, 2);
            if ((lane & 3) == 0)
                psum[(wm * 64 + mt * 16 + (lane >> 2) + h * 8) * 2 + wn] = s;
        }
    __syncthreads();
    part[((size_t)b * kNQ + m0 + threadIdx.x) * 32 + blockIdx.x] =
        psum[threadIdx.x * 2] + psum[threadIdx.x * 2 + 1];
}

__global__ __launch_bounds__(128, 2)
void gemm_pv_k(const __half* __restrict__ Ph, const __half* __restrict__ Vt,
               const float* __restrict__ idt,
               const float* __restrict__ awp, const float* __restrict__ owp,
               float* __restrict__ out) {
    extern __shared__ char smem[];
    const int m0 = blockIdx.y * 128;
    const int n0 = blockIdx.x * 128;
    const int b  = m0 / kNQ;
    float acc[4][8][4] = {};
    hmma_mainloop(Ph + (size_t)m0 * kNS, Vt + ((size_t)b * kD + n0) * kNS,
                  kNS, kNS, kNS, smem, acc);
    const int wid = threadIdx.x >> 5, lane = threadIdx.x & 31;
    const int wm = wid >> 1, wn = wid & 1;
    const float aw = awp[0], ow = owp[0];
    #pragma unroll
    for (int mt = 0; mt < 4; ++mt) {
        const int r0 = m0 + wm * 64 + mt * 16 + (lane >> 2);
        #pragma unroll
        for (int nt = 0; nt < 8; ++nt) {
            const int c = n0 + wn * 64 + nt * 8 + (lane & 3) * 2;
            const float* a = acc[mt][nt];
            const float2 d0 = *(const float2*)(idt + (size_t)r0 * kD + c);
            const float2 d1 = *(const float2*)(idt + (size_t)(r0 + 8) * kD + c);
            *(float2*)(out + (size_t)r0 * kD + c) =
                make_float2(aw * a[0] + ow * d0.x, aw * a[1] + ow * d0.y);
            *(float2*)(out + (size_t)(r0 + 8) * kD + c) =
                make_float2(aw * a[2] + ow * d1.x, aw * a[3] + ow * d1.y);
        }
    }
}

// ---------------- support kernels ----------------
__device__ __forceinline__ float block_reduce_sum(float v) {
    __shared__ float red[32];
    __shared__ float total;
    #pragma unroll
    for (int o = 16; o > 0; o >>= 1) v += __shfl_down_sync(0xffffffffu, v, o);
    const int lane = threadIdx.x & 31, w = threadIdx.x >> 5;
    if (lane == 0) red[w] = v;
    __syncthreads();
    if (w == 0) {
        v = (lane < (int)(blockDim.x >> 5)) ? red[lane] : 0.0f;
        #pragma unroll
        for (int o = 16; o > 0; o >>= 1) v += __shfl_down_sync(0xffffffffu, v, o);
        if (lane == 0) total = v;
    }
    __syncthreads();
    return total;
}

__global__ void to_half(const float* __restrict__ x, __half* __restrict__ hi, size_t n4) {
    const size_t i = (size_t)blockIdx.x * blockDim.x + threadIdx.x;
    if (i >= n4) return;
    const float4 v = ((const float4*)x)[i];
    ((__half2*)hi)[2 * i]     = __floats2half2_rn(v.x, v.y);
    ((__half2*)hi)[2 * i + 1] = __floats2half2_rn(v.z, v.w);
}

__global__ void make_E(const float* __restrict__ W, __half* __restrict__ E) {
    const size_t i = (size_t)blockIdx.x * blockDim.x + threadIdx.x;   // float4 idx
    const size_t base = i * 4;
    if (base >= (size_t)kC * kC) return;
    float4 w = *(const float4*)(W + base);
    const int n = (int)(base / kC);
    const int c = (int)(base % kC);
    if (n == c)     w.x -= 1.0f;
    if (n == c + 1) w.y -= 1.0f;
    if (n == c + 2) w.z -= 1.0f;
    if (n == c + 3) w.w -= 1.0f;
    ((__half2*)E)[2 * i]     = __floats2half2_rn(w.x, w.y);
    ((__half2*)E)[2 * i + 1] = __floats2half2_rn(w.z, w.w);
}

// row l2norm of fp32 rows (len kC) -> fp16
__global__ void l2norm_h(const float* __restrict__ src, __half* __restrict__ hi) {
    const float* p = src + (size_t)blockIdx.x * kC;
    float ss = 0.0f;
    #pragma unroll
    for (int i = threadIdx.x * 4; i < kC; i += 1024) {
        const float4 v = *(const float4*)(p + i);
        ss += v.x * v.x + v.y * v.y + v.z * v.z + v.w * v.w;
    }
    const float tot = block_reduce_sum(ss);
    const float inv = 1.0f / fmaxf(sqrtf(tot), 1e-12f);
    __half* ho = hi + (size_t)blockIdx.x * kC;
    #pragma unroll
    for (int i = threadIdx.x * 4; i < kC; i += 1024) {
        const float4 v = *(const float4*)(p + i);
        *(__half2*)(ho + i)     = __floats2half2_rn(v.x * inv, v.y * inv);
        *(__half2*)(ho + i + 2) = __floats2half2_rn(v.z * inv, v.w * inv);
    }
}

__global__ void transpose_v(const float* __restrict__ v, __half* __restrict__ vt) {
    __shared__ float t[32][33];
    const int b  = blockIdx.z;
    const int s0 = blockIdx.x * 32;
    const int d0 = blockIdx.y * 32;
    const int tx = threadIdx.x, ty = threadIdx.y;
    #pragma unroll
    for (int i = 0; i < 32; i += 8)
        t[ty + i][tx] = v[((size_t)b * kNS + s0 + ty + i) * kD + d0 + tx];
    __syncthreads();
    #pragma unroll
    for (int i = 0; i < 32; i += 8)
        vt[((size_t)b * kD + d0 + ty + i) * kNS + s0 + tx] = __float2half_rn(t[tx][ty + i]);
}

// reduce 32 per-block partials per row -> rowsum (deterministic fixed order)
__global__ void rowsum_reduce(const float* __restrict__ part, float* __restrict__ rs) {
    const int r = blockIdx.x * 256 + threadIdx.x;
    const float* p = part + (size_t)r * 32;
    float s = 0.0f;
    #pragma unroll
    for (int j = 0; j < 32; ++j) s += p[j];
    rs[r] = s;
}

// Normalize attn in place AND emit fp16 normalized weights for PV.
__global__ void attn_norm(float* __restrict__ P, const float* __restrict__ rs,
                          __half* __restrict__ Ph) {
    const size_t e = ((size_t)blockIdx.x * blockDim.x + threadIdx.x) * 4;
    const float inv = 1.0f / rs[e / kNS];
    float4 x = *(const float4*)(P + e);
    x.x *= inv; x.y *= inv; x.z *= inv; x.w *= inv;
    *(float4*)(P + e) = x;
    *(__half2*)(Ph + e)     = __floats2half2_rn(x.x, x.y);
    *(__half2*)(Ph + e + 2) = __floats2half2_rn(x.z, x.w);
}

// ---------------- launch ----------------
extern "C" void kernel_launch(void* const* d_in, const int* in_sizes, int n_in,
                              void* d_out, int out_size) {
    (void)in_sizes; (void)n_in; (void)out_size;
    const float* k     = (const float*)d_in[0];
    const float* v     = (const float*)d_in[1];
    const float* q     = (const float*)d_in[2];
    const float* idt   = (const float*)d_in[3];
    const float* mask  = (const float*)d_in[4];
    const float* W     = (const float*)d_in[5];
    const float* bias  = (const float*)d_in[6];
    const float* scale = (const float*)d_in[7];
    const float* attwt = (const float*)d_in[8];
    const float* orgwt = (const float*)d_in[9];

    float* out  = (float*)d_out;
    float* attn = out + (size_t)kB * kNQ * kD;

    __half *ah, *bh, *eh, *vt, *ph;
    float *qp, *kp, *rs, *part;
    cudaGetSymbolAddress((void**)&ah, g_ah);
    cudaGetSymbolAddress((void**)&bh, g_bh);
    cudaGetSymbolAddress((void**)&eh, g_eh);
    cudaGetSymbolAddress((void**)&vt, g_vt);
    cudaGetSymbolAddress((void**)&ph, g_ph);
    cudaGetSymbolAddress((void**)&qp, g_qp);
    cudaGetSymbolAddress((void**)&kp, g_kp);
    cudaGetSymbolAddress((void**)&rs, g_rowsum);
    cudaGetSymbolAddress((void**)&part, g_part);

    static bool attr_done = false;
    if (!attr_done) {
        cudaFuncSetAttribute(gemm_proj_k, cudaFuncAttributeMaxDynamicSharedMemorySize, SMEM_GM);
        cudaFuncSetAttribute(gemm_attn_k, cudaFuncAttributeMaxDynamicSharedMemorySize, SMEM_GM);
        cudaFuncSetAttribute(gemm_pv_k,   cudaFuncAttributeMaxDynamicSharedMemorySize, SMEM_GM);
        attr_done = true;
    }

    const size_t nq4 = (size_t)kMQ * kC / 4;
    to_half<<<(unsigned)((nq4 + 255) / 256), 256>>>(q, ah, nq4);
    to_half<<<(unsigned)((nq4 + 255) / 256), 256>>>(k, bh, nq4);
    const size_t nw4 = (size_t)kC * kC / 4;
    make_E<<<(unsigned)((nw4 + 255) / 256), 256>>>(W, eh);
    transpose_v<<<dim3(kNS / 32, kD / 32, kB), dim3(32, 8)>>>(v, vt);

    gemm_proj_k<<<dim3(kC / 128, kMQ / 128), 128, SMEM_GM>>>(ah, eh, q, bias, qp);
    gemm_proj_k<<<dim3(kC / 128, kMK / 128), 128, SMEM_GM>>>(bh, eh, k, bias, kp);

    l2norm_h<<<kMQ, 256>>>(qp, ah);
    l2norm_h<<<kMK, 256>>>(kp, bh);

    gemm_attn_k<<<dim3(kNS / 128, kNQ / 128, kB), 128, SMEM_GM>>>(ah, bh, mask, scale,
                                                                  attn, part);
    rowsum_reduce<<<kMQ / 256, 256>>>(part, rs);

    const size_t nvec4 = (size_t)kB * kNQ * kNS / 4;
    attn_norm<<<(unsigned)(nvec4 / 256), 256>>>(attn, rs, ph);

    gemm_pv_k<<<dim3(kD / 128, kMQ / 128), 128, SMEM_GM>>>(ph, vt, idt, attwt, orgwt, out);
}

// round 12
// speedup vs baseline: 1.5344x; 1.5344x over previous
#include <cuda_runtime.h>
#include <cuda_fp16.h>
#include <math.h>
#include <stdint.h>

constexpr int kB  = 8;
constexpr int kNQ = 4096;
constexpr int kNS = 4096;
constexpr int kC  = 2048;
constexpr int kD  = 512;
constexpr int kMQ = kB * kNQ;   // 32768
constexpr int kMK = kB * kNS;   // 32768

// Scratch (__device__ globals; allocation-free rule)
__device__ __half g_ah[(size_t)kMQ * kC];        // q hi -> later qp hi (full)
__device__ __half g_bh[(size_t)kMK * kC];        // k compact fp16 -> later kp-hat compact
__device__ __half g_eh[(size_t)kC * kC];         // E = W - I, fp16
__device__ __half g_vt[(size_t)kB * kD * kNS];   // v gathered+transposed [b, d, j] fp16
__device__ __half g_ph[(size_t)kMQ * kNS];       // normalized attn weights, compact cols
__device__ float  g_qp[(size_t)kMQ * kC];
__device__ float  g_kp[(size_t)kMK * kC];        // kp compact fp32
__device__ float  g_part[(size_t)kMQ * 32];
__device__ float  g_rowsum[kMQ];
__device__ int    g_pos[kB * kNS];               // exclusive prefix of valid
__device__ int    g_vidx[kB * kNS];              // compact j -> original s
__device__ int    g_cnt[kB];
__device__ int    g_cntpad[kB];                  // cnt rounded up to 128

// ---------------- helpers ----------------
__device__ __forceinline__ uint32_t smem_u32(const void* p) {
    uint32_t a;
    asm("{ .reg .u64 t; cvta.to.shared.u64 t, %1; cvt.u32.u64 %0, t; }" : "=r"(a) : "l"(p));
    return a;
}
__device__ __forceinline__ void ldm4(uint32_t r[4], uint32_t addr) {
    asm volatile("ldmatrix.sync.aligned.m8n8.x4.shared.b16 {%0,%1,%2,%3}, [%4];"
                 : "=r"(r[0]), "=r"(r[1]), "=r"(r[2]), "=r"(r[3]) : "r"(addr));
}
__device__ __forceinline__ void mma16816(float c[4], const uint32_t a[4],
                                         uint32_t b0, uint32_t b1) {
    asm volatile(
        "mma.sync.aligned.m16n8k16.row.col.f32.f16.f16.f32 "
        "{%0,%1,%2,%3}, {%4,%5,%6,%7}, {%8,%9}, {%0,%1,%2,%3};"
        : "+f"(c[0]), "+f"(c[1]), "+f"(c[2]), "+f"(c[3])
        : "r"(a[0]), "r"(a[1]), "r"(a[2]), "r"(a[3]), "r"(b0), "r"(b1));
}

// Tile geometry: block 128x128, BK=64 fp16, rows padded to 144 B (R9 config)
constexpr int BK = 64;
constexpr uint32_t ROWB = 144;
constexpr uint32_t TS   = 128 * ROWB;          // 18432 B per tile
constexpr unsigned SMEM_GM = 4 * TS;           // 73728: 2 stages x (A + B)

__device__ __forceinline__ void load_tile(uint32_t dst, const __half* src, int ldk) {
    const int tid = threadIdx.x;
    #pragma unroll
    for (int i = 0; i < 4; ++i) {
        const int idx = tid + i * 256;
        const int row = idx >> 3;
        const int seg = idx & 7;
        asm volatile("cp.async.cg.shared.global [%0], [%1], 16;"
                     :: "r"(dst + row * ROWB + seg * 16),
                        "l"(src + (size_t)row * ldk + seg * 8) : "memory");
    }
}

// HMMA mainloop (exact R9): 8 warps as 4(m) x 2(n); warp tile 32x64; 2-stage.
__device__ __forceinline__ void hmma_mainloop(
    const __half* A, const __half* B, int lda, int ldb, int K,
    char* smem, float acc[2][8][4])
{
    const int tid  = threadIdx.x;
    const int wid  = tid >> 5;
    const int lane = tid & 31;
    const int wm   = wid >> 1;
    const int wn   = wid & 1;
    constexpr uint32_t STAGE = 2 * TS;
    const uint32_t sb = smem_u32(smem);
    const int NK = K / BK;

    load_tile(sb, A, lda);
    load_tile(sb + TS, B, ldb);
    asm volatile("cp.async.commit_group;");

    const uint32_t lane_off = (uint32_t)((lane & 15) * ROWB + ((lane >> 4) * 8) * 2);

    for (int kc = 0; kc < NK; ++kc) {
        if (kc + 1 < NK) {
            const uint32_t s = sb + ((kc + 1) & 1) * STAGE;
            const size_t k0 = (size_t)(kc + 1) * BK;
            load_tile(s, A + k0, lda);
            load_tile(s + TS, B + k0, ldb);
            asm volatile("cp.async.commit_group;");
            asm volatile("cp.async.wait_group 1;");
        } else {
            asm volatile("cp.async.wait_group 0;");
        }
        __syncthreads();

        const uint32_t abase = sb + (kc & 1) * STAGE + wm * 32 * ROWB + lane_off;
        const uint32_t bbase = sb + (kc & 1) * STAGE + TS + wn * 64 * ROWB + lane_off;

        #pragma unroll
        for (int ks = 0; ks < 4; ++ks) {
            const uint32_t kb = ks * 32;
            uint32_t ah[2][4], bh[4][4];
            #pragma unroll
            for (int mt = 0; mt < 2; ++mt)
                ldm4(ah[mt], abase + mt * 16 * ROWB + kb);
            #pragma unroll
            for (int np = 0; np < 4; ++np)
                ldm4(bh[np], bbase + np * 16 * ROWB + kb);
            #pragma unroll
            for (int mt = 0; mt < 2; ++mt)
                #pragma unroll
                for (int np = 0; np < 4; ++np)
                    #pragma unroll
                    for (int h = 0; h < 2; ++h)
                        mma16816(acc[mt][np * 2 + h], ah[mt], bh[np][h], bh[np][h + 2]);
        }
        __syncthreads();
    }
}

// ---------------- mask scan (deterministic per-batch prefix sum) ----------------
__global__ void mask_scan(const float* __restrict__ mask, int* __restrict__ pos,
                          int* __restrict__ vidx, int* __restrict__ cnt,
                          int* __restrict__ cntpad) {
    __shared__ int wsum[32];
    const int b = blockIdx.x;
    const int tid = threadIdx.x;            // 1024 threads, 4 elems each
    const float* m = mask + (size_t)b * kNS;
    int v[4], local = 0;
    #pragma unroll
    for (int i = 0; i < 4; ++i) { v[i] = (m[tid * 4 + i] == 0.0f) ? 1 : 0; local += v[i]; }
    const int lane = tid & 31, w = tid >> 5;
    int pre = local;
    #pragma unroll
    for (int o = 1; o < 32; o <<= 1) {
        int t = __shfl_up_sync(0xffffffffu, pre, o);
        if (lane >= o) pre += t;
    }
    if (lane == 31) wsum[w] = pre;
    __syncthreads();
    if (w == 0) {
        int t = wsum[lane];
        #pragma unroll
        for (int o = 1; o < 32; o <<= 1) {
            int u = __shfl_up_sync(0xffffffffu, t, o);
            if (lane >= o) t += u;
        }
        wsum[lane] = t;
    }
    __syncthreads();
    int base = (w > 0 ? wsum[w - 1] : 0) + (pre - local);
    #pragma unroll
    for (int i = 0; i < 4; ++i) {
        const int s = tid * 4 + i;
        pos[b * kNS + s] = base;
        if (v[i]) { vidx[b * kNS + base] = s; base++; }
    }
    if (tid == 1023) {
        const int total = wsum[31];
        cnt[b] = total;
        cntpad[b] = ((total + 127) >> 7) << 7;
    }
}

// ---------------- GEMM kernels ----------------
// q projection (full): Y = q + q@E^T + bias
__global__ __launch_bounds__(256, 2)
void gemm_proj_k(const __half* __restrict__ Xh, const __half* __restrict__ Eh,
                 const float* __restrict__ x32, const float* __restrict__ bias,
                 float* __restrict__ Y) {
    extern __shared__ char smem[];
    const int m0 = blockIdx.y * 128, n0 = blockIdx.x * 128;
    float acc[2][8][4] = {};
    hmma_mainloop(Xh + (size_t)m0 * kC, Eh + (size_t)n0 * kC, kC, kC, kC, smem, acc);
    const int wid = threadIdx.x >> 5, lane = threadIdx.x & 31;
    const int wm = wid >> 1, wn = wid & 1;
    #pragma unroll
    for (int mt = 0; mt < 2; ++mt)
        #pragma unroll
        for (int nt = 0; nt < 8; ++nt) {
            const int r0 = m0 + wm * 32 + mt * 16 + (lane >> 2);
            const int c  = n0 + wn * 64 + nt * 8 + (lane & 3) * 2;
            const float* a = acc[mt][nt];
            const float2 x0 = *(const float2*)(x32 + (size_t)r0 * kC + c);
            const float2 x1 = *(const float2*)(x32 + (size_t)(r0 + 8) * kC + c);
            *(float2*)(Y + (size_t)r0 * kC + c) =
                make_float2(a[0] + x0.x + bias[c], a[1] + x0.y + bias[c + 1]);
            *(float2*)(Y + (size_t)(r0 + 8) * kC + c) =
                make_float2(a[2] + x1.x + bias[c], a[3] + x1.y + bias[c + 1]);
        }
}

// k projection on COMPACT rows: Y[b,j] = k[b,vidx[j]] + kc@E^T + bias (j<cnt), else 0
__global__ __launch_bounds__(256, 2)
void gemm_projk_k(const __half* __restrict__ Kc, const __half* __restrict__ Eh,
                  const float* __restrict__ kf, const int* __restrict__ vidx,
                  const int* __restrict__ cnt, const int* __restrict__ cntpad,
                  const float* __restrict__ bias, float* __restrict__ Y) {
    extern __shared__ char smem[];
    const int b = blockIdx.z;
    const int m0 = blockIdx.y * 128;
    if (m0 >= cntpad[b]) return;
    const int n0 = blockIdx.x * 128;
    float acc[2][8][4] = {};
    hmma_mainloop(Kc + ((size_t)b * kNS + m0) * kC, Eh + (size_t)n0 * kC,
                  kC, kC, kC, smem, acc);
    const int cn = cnt[b];
    const int wid = threadIdx.x >> 5, lane = threadIdx.x & 31;
    const int wm = wid >> 1, wn = wid & 1;
    #pragma unroll
    for (int mt = 0; mt < 2; ++mt)
        #pragma unroll
        for (int nt = 0; nt < 8; ++nt) {
            const int j0 = m0 + wm * 32 + mt * 16 + (lane >> 2);
            const int c  = n0 + wn * 64 + nt * 8 + (lane & 3) * 2;
            const float* a = acc[mt][nt];
            #pragma unroll
            for (int hh = 0; hh < 2; ++hh) {
                const int j = j0 + hh * 8;
                float2 o = make_float2(0.0f, 0.0f);
                if (j < cn) {
                    const float* x = kf + ((size_t)b * kNS + vidx[b * kNS + j]) * kC + c;
                    o.x = a[hh * 2 + 0] + x[0] + bias[c];
                    o.y = a[hh * 2 + 1] + x[1] + bias[c + 1];
                }
                *(float2*)(Y + ((size_t)b * kNS + j) * kC + c) = o;
            }
        }
}

// QK^T over COMPACT k columns + exp epilogue + partial row sums.
// Padding columns (>= cnt) forced to exactly 0 (keeps rowsum exact).
__global__ __launch_bounds__(256, 2)
void gemm_attn_k(const __half* __restrict__ qh, const __half* __restrict__ khc,
                 const float* __restrict__ scale_ptr, const int* __restrict__ cnt,
                 const int* __restrict__ cntpad,
                 float* __restrict__ Pc, float* __restrict__ part) {
    extern __shared__ char smem[];
    const int b = blockIdx.z;
    const int n0 = blockIdx.x * 128;
    if (n0 >= cntpad[b]) return;
    const int m0 = blockIdx.y * 128;
    const size_t aoff = ((size_t)b * kNQ + m0) * kC;
    const size_t boff = ((size_t)b * kNS + n0) * kC;
    float acc[2][8][4] = {};
    hmma_mainloop(qh + aoff, khc + boff, kC, kC, kC, smem, acc);
    const int cn = cnt[b];
    const int wid = threadIdx.x >> 5, lane = threadIdx.x & 31;
    const int wm = wid >> 1, wn = wid & 1;
    const float sc = scale_ptr[0];
    float srow[2][2] = {};
    #pragma unroll
    for (int mt = 0; mt < 2; ++mt)
        #pragma unroll
        for (int nt = 0; nt < 8; ++nt) {
            const int r0 = m0 + wm * 32 + mt * 16 + (lane >> 2);
            const int c  = n0 + wn * 64 + nt * 8 + (lane & 3) * 2;
            const float* a = acc[mt][nt];
            const float e0 = (c     < cn) ? __expf(sc * a[0] - sc) : 0.0f;
            const float e1 = (c + 1 < cn) ? __expf(sc * a[1] - sc) : 0.0f;
            const float e2 = (c     < cn) ? __expf(sc * a[2] - sc) : 0.0f;
            const float e3 = (c + 1 < cn) ? __expf(sc * a[3] - sc) : 0.0f;
            const size_t rb0 = ((size_t)b * kNQ + r0) * kNS + c;
            const size_t rb1 = rb0 + (size_t)8 * kNS;
            *(float2*)(Pc + rb0) = make_float2(e0, e1);
            *(float2*)(Pc + rb1) = make_float2(e2, e3);
            srow[mt][0] += e0 + e1;
            srow[mt][1] += e2 + e3;
        }
    float* psum = (float*)smem;   // [128][2]
    #pragma unroll
    for (int mt = 0; mt < 2; ++mt)
        #pragma unroll
        for (int h = 0; h < 2; ++h) {
            float s = srow[mt][h];
            s += __shfl_down_sync(0xffffffffu, s, 1);
            s += __shfl_down_sync(0xffffffffu, s, 2);
            if ((lane & 3) == 0)
                psum[(wm * 32 + mt * 16 + (lane >> 2) + h * 8) * 2 + wn] = s;
        }
    __syncthreads();
    if (threadIdx.x < 128)
        part[((size_t)b * kNQ + m0 + threadIdx.x) * 32 + blockIdx.x] =
            psum[threadIdx.x * 2] + psum[threadIdx.x * 2 + 1];
}

// PV over compact support: K = cntpad[b]
__global__ __launch_bounds__(256, 2)
void gemm_pv_k(const __half* __restrict__ Phc, const __half* __restrict__ Vt,
               const float* __restrict__ idt, const int* __restrict__ cntpad,
               const float* __restrict__ awp, const float* __restrict__ owp,
               float* __restrict__ out) {
    extern __shared__ char smem[];
    const int m0 = blockIdx.y * 128;
    const int n0 = blockIdx.x * 128;
    const int b  = m0 / kNQ;
    const int K  = cntpad[b];
    float acc[2][8][4] = {};
    hmma_mainloop(Phc + (size_t)m0 * kNS, Vt + ((size_t)b * kD + n0) * kNS,
                  kNS, kNS, K, smem, acc);
    const int wid = threadIdx.x >> 5, lane = threadIdx.x & 31;
    const int wm = wid >> 1, wn = wid & 1;
    const float aw = awp[0], ow = owp[0];
    #pragma unroll
    for (int mt = 0; mt < 2; ++mt) {
        const int r0 = m0 + wm * 32 + mt * 16 + (lane >> 2);
        #pragma unroll
        for (int nt = 0; nt < 8; ++nt) {
            const int c = n0 + wn * 64 + nt * 8 + (lane & 3) * 2;
            const float* a = acc[mt][nt];
            const float2 d0 = *(const float2*)(idt + (size_t)r0 * kD + c);
            const float2 d1 = *(const float2*)(idt + (size_t)(r0 + 8) * kD + c);
            *(float2*)(out + (size_t)r0 * kD + c) =
                make_float2(aw * a[0] + ow * d0.x, aw * a[1] + ow * d0.y);
            *(float2*)(out + (size_t)(r0 + 8) * kD + c) =
                make_float2(aw * a[2] + ow * d1.x, aw * a[3] + ow * d1.y);
        }
    }
}

// ---------------- support kernels ----------------
__device__ __forceinline__ float block_reduce_sum(float v) {
    __shared__ float red[32];
    __shared__ float total;
    #pragma unroll
    for (int o = 16; o > 0; o >>= 1) v += __shfl_down_sync(0xffffffffu, v, o);
    const int lane = threadIdx.x & 31, w = threadIdx.x >> 5;
    if (lane == 0) red[w] = v;
    __syncthreads();
    if (w == 0) {
        v = (lane < (int)(blockDim.x >> 5)) ? red[lane] : 0.0f;
        #pragma unroll
        for (int o = 16; o > 0; o >>= 1) v += __shfl_down_sync(0xffffffffu, v, o);
        if (lane == 0) total = v;
    }
    __syncthreads();
    return total;
}

__global__ void to_half(const float* __restrict__ x, __half* __restrict__ hi, size_t n4) {
    const size_t i = (size_t)blockIdx.x * blockDim.x + threadIdx.x;
    if (i >= n4) return;
    const float4 v = ((const float4*)x)[i];
    ((__half2*)hi)[2 * i]     = __floats2half2_rn(v.x, v.y);
    ((__half2*)hi)[2 * i + 1] = __floats2half2_rn(v.z, v.w);
}

// gather valid k rows -> compact fp16 (zeros for padding rows)
__global__ void gather_k_half(const float* __restrict__ k, const int* __restrict__ vidx,
                              const int* __restrict__ cnt, const int* __restrict__ cntpad,
                              __half* __restrict__ kc) {
    const int b = blockIdx.y, j = blockIdx.x;
    if (j >= cntpad[b]) return;
    __half* dst = kc + ((size_t)b * kNS + j) * kC;
    if (j >= cnt[b]) {
        for (int i = threadIdx.x * 4; i < kC; i += 1024) {
            *(__half2*)(dst + i)     = __floats2half2_rn(0.0f, 0.0f);
            *(__half2*)(dst + i + 2) = __floats2half2_rn(0.0f, 0.0f);
        }
        return;
    }
    const float* src = k + ((size_t)b * kNS + vidx[b * kNS + j]) * kC;
    for (int i = threadIdx.x * 4; i < kC; i += 1024) {
        const float4 v = *(const float4*)(src + i);
        *(__half2*)(dst + i)     = __floats2half2_rn(v.x, v.y);
        *(__half2*)(dst + i + 2) = __floats2half2_rn(v.z, v.w);
    }
}

__global__ void make_E(const float* __restrict__ W, __half* __restrict__ E) {
    const size_t i = (size_t)blockIdx.x * blockDim.x + threadIdx.x;
    const size_t base = i * 4;
    if (base >= (size_t)kC * kC) return;
    float4 w = *(const float4*)(W + base);
    const int n = (int)(base / kC);
    const int c = (int)(base % kC);
    if (n == c)     w.x -= 1.0f;
    if (n == c + 1) w.y -= 1.0f;
    if (n == c + 2) w.z -= 1.0f;
    if (n == c + 3) w.w -= 1.0f;
    ((__half2*)E)[2 * i]     = __floats2half2_rn(w.x, w.y);
    ((__half2*)E)[2 * i + 1] = __floats2half2_rn(w.z, w.w);
}

// row l2norm (full, for qp)
__global__ void l2norm_h(const float* __restrict__ src, __half* __restrict__ hi) {
    const float* p = src + (size_t)blockIdx.x * kC;
    float ss = 0.0f;
    #pragma unroll
    for (int i = threadIdx.x * 4; i < kC; i += 1024) {
        const float4 v = *(const float4*)(p + i);
        ss += v.x * v.x + v.y * v.y + v.z * v.z + v.w * v.w;
    }
    const float tot = block_reduce_sum(ss);
    const float inv = 1.0f / fmaxf(sqrtf(tot), 1e-12f);
    __half* ho = hi + (size_t)blockIdx.x * kC;
    #pragma unroll
    for (int i = threadIdx.x * 4; i < kC; i += 1024) {
        const float4 v = *(const float4*)(p + i);
        *(__half2*)(ho + i)     = __floats2half2_rn(v.x * inv, v.y * inv);
        *(__half2*)(ho + i + 2) = __floats2half2_rn(v.z * inv, v.w * inv);
    }
}

// row l2norm for compact kp rows; padding rows -> exact zeros
__global__ void l2norm_k(const float* __restrict__ src, __half* __restrict__ hi,
                         const int* __restrict__ cnt, const int* __restrict__ cntpad) {
    const int b = blockIdx.x >> 12;
    const int j = blockIdx.x & (kNS - 1);
    if (j >= cntpad[b]) return;
    __half* ho = hi + ((size_t)b * kNS + j) * kC;
    if (j >= cnt[b]) {
        for (int i = threadIdx.x * 4; i < kC; i += 1024) {
            *(__half2*)(ho + i)     = __floats2half2_rn(0.0f, 0.0f);
            *(__half2*)(ho + i + 2) = __floats2half2_rn(0.0f, 0.0f);
        }
        return;
    }
    const float* p = src + ((size_t)b * kNS + j) * kC;
    float ss = 0.0f;
    #pragma unroll
    for (int i = threadIdx.x * 4; i < kC; i += 1024) {
        const float4 v = *(const float4*)(p + i);
        ss += v.x * v.x + v.y * v.y + v.z * v.z + v.w * v.w;
    }
    const float tot = block_reduce_sum(ss);
    const float inv = 1.0f / fmaxf(sqrtf(tot), 1e-12f);
    #pragma unroll
    for (int i = threadIdx.x * 4; i < kC; i += 1024) {
        const float4 v = *(const float4*)(p + i);
        *(__half2*)(ho + i)     = __floats2half2_rn(v.x * inv, v.y * inv);
        *(__half2*)(ho + i + 2) = __floats2half2_rn(v.z * inv, v.w * inv);
    }
}

// gather+transpose valid v rows -> vt[b, d, j] fp16 (padding j -> 0)
__global__ void transpose_v_g(const float* __restrict__ v, const int* __restrict__ vidx,
                              const int* __restrict__ cnt, const int* __restrict__ cntpad,
                              __half* __restrict__ vt) {
    __shared__ float t[32][33];
    const int b  = blockIdx.z;
    const int j0 = blockIdx.x * 32;
    if (j0 >= cntpad[b]) return;
    const int d0 = blockIdx.y * 32;
    const int cn = cnt[b];
    const int tx = threadIdx.x, ty = threadIdx.y;
    #pragma unroll
    for (int i = 0; i < 32; i += 8) {
        const int j = j0 + ty + i;
        float val = 0.0f;
        if (j < cn) val = v[((size_t)b * kNS + vidx[b * kNS + j]) * kD + d0 + tx];
        t[ty + i][tx] = val;
    }
    __syncthreads();
    #pragma unroll
    for (int i = 0; i < 32; i += 8)
        vt[((size_t)b * kD + d0 + ty + i) * kNS + j0 + tx] = __float2half_rn(t[tx][ty + i]);
}

// rowsum from partials (only active column blocks)
__global__ void rowsum_reduce(const float* __restrict__ part, const int* __restrict__ cntpad,
                              float* __restrict__ rs) {
    const int r = blockIdx.x * 256 + threadIdx.x;
    const int nb = cntpad[r >> 12] >> 7;
    const float* p = part + (size_t)r * 32;
    float s = 0.0f;
    for (int j = 0; j < nb; ++j) s += p[j];
    rs[r] = s;
}

// Normalize + scatter: read compact P row, write full attn row (zeros where masked)
// and compact normalized fp16 weights for PV.
__global__ void norm_scatter(float* __restrict__ P, const float* __restrict__ rs,
                             const int* __restrict__ pos, const int* __restrict__ cntpad,
                             const float* __restrict__ mask, __half* __restrict__ Phc) {
    extern __shared__ float srow[];
    const int row = blockIdx.x;
    const int b = row >> 12;
    const int cp = cntpad[b];
    float* prow = P + (size_t)row * kNS;
    for (int i = threadIdx.x; i < cp; i += 256) srow[i] = prow[i];
    __syncthreads();
    const float inv = 1.0f / rs[row];
    __half* ph = Phc + (size_t)row * kNS;
    for (int i = threadIdx.x; i < cp; i += 256)
        ph[i] = __float2half_rn(srow[i] * inv);
    const int* posb = pos + b * kNS;
    const float* mb = mask + b * kNS;
    for (int s = threadIdx.x; s < kNS; s += 256)
        prow[s] = (mb[s] == 0.0f) ? srow[posb[s]] * inv : 0.0f;
}

// ---------------- launch ----------------
extern "C" void kernel_launch(void* const* d_in, const int* in_sizes, int n_in,
                              void* d_out, int out_size) {
    (void)in_sizes; (void)n_in; (void)out_size;
    const float* k     = (const float*)d_in[0];
    const float* v     = (const float*)d_in[1];
    const float* q     = (const float*)d_in[2];
    const float* idt   = (const float*)d_in[3];
    const float* mask  = (const float*)d_in[4];
    const float* W     = (const float*)d_in[5];
    const float* bias  = (const float*)d_in[6];
    const float* scale = (const float*)d_in[7];
    const float* attwt = (const float*)d_in[8];
    const float* orgwt = (const float*)d_in[9];

    float* out  = (float*)d_out;
    float* attn = out + (size_t)kB * kNQ * kD;

    __half *ah, *bh, *eh, *vt, *ph;
    float *qp, *kp, *rs, *part;
    int *pos, *vidx, *cnt, *cntpad;
    cudaGetSymbolAddress((void**)&ah, g_ah);
    cudaGetSymbolAddress((void**)&bh, g_bh);
    cudaGetSymbolAddress((void**)&eh, g_eh);
    cudaGetSymbolAddress((void**)&vt, g_vt);
    cudaGetSymbolAddress((void**)&ph, g_ph);
    cudaGetSymbolAddress((void**)&qp, g_qp);
    cudaGetSymbolAddress((void**)&kp, g_kp);
    cudaGetSymbolAddress((void**)&rs, g_rowsum);
    cudaGetSymbolAddress((void**)&part, g_part);
    cudaGetSymbolAddress((void**)&pos, g_pos);
    cudaGetSymbolAddress((void**)&vidx, g_vidx);
    cudaGetSymbolAddress((void**)&cnt, g_cnt);
    cudaGetSymbolAddress((void**)&cntpad, g_cntpad);

    static bool attr_done = false;
    if (!attr_done) {
        cudaFuncSetAttribute(gemm_proj_k,  cudaFuncAttributeMaxDynamicSharedMemorySize, SMEM_GM);
        cudaFuncSetAttribute(gemm_projk_k, cudaFuncAttributeMaxDynamicSharedMemorySize, SMEM_GM);
        cudaFuncSetAttribute(gemm_attn_k,  cudaFuncAttributeMaxDynamicSharedMemorySize, SMEM_GM);
        cudaFuncSetAttribute(gemm_pv_k,    cudaFuncAttributeMaxDynamicSharedMemorySize, SMEM_GM);
        attr_done = true;
    }

    mask_scan<<<kB, 1024>>>(mask, pos, vidx, cnt, cntpad);

    const size_t nq4 = (size_t)kMQ * kC / 4;
    to_half<<<(unsigned)((nq4 + 255) / 256), 256>>>(q, ah, nq4);
    gather_k_half<<<dim3(kNS, kB), 256>>>(k, vidx, cnt, cntpad, bh);
    const size_t nw4 = (size_t)kC * kC / 4;
    make_E<<<(unsigned)((nw4 + 255) / 256), 256>>>(W, eh);
    transpose_v_g<<<dim3(kNS / 32, kD / 32, kB), dim3(32, 8)>>>(v, vidx, cnt, cntpad, vt);

    gemm_proj_k<<<dim3(kC / 128, kMQ / 128), 256, SMEM_GM>>>(ah, eh, q, bias, qp);
    gemm_projk_k<<<dim3(kC / 128, kNS / 128, kB), 256, SMEM_GM>>>(bh, eh, k, vidx, cnt,
                                                                  cntpad, bias, kp);

    l2norm_h<<<kMQ, 256>>>(qp, ah);
    l2norm_k<<<kMK, 256>>>(kp, bh, cnt, cntpad);

    gemm_attn_k<<<dim3(kNS / 128, kNQ / 128, kB), 256, SMEM_GM>>>(ah, bh, scale, cnt,
                                                                  cntpad, attn, part);
    rowsum_reduce<<<kMQ / 256, 256>>>(part, cntpad, rs);
    norm_scatter<<<kMQ, 256, kNS * 4>>>(attn, rs, pos, cntpad, mask, ph);

    gemm_pv_k<<<dim3(kD / 128, kMQ / 128), 256, SMEM_GM>>>(ph, vt, idt, cntpad,
                                                           attwt, orgwt, out);
}